// round 15
// baseline (speedup 1.0000x reference)
#include <cuda_runtime.h>
#include <cuda_bf16.h>
#include <cuda_fp16.h>
#include <cstdint>
#include <stdint.h>
#include <math.h>

typedef unsigned long long u64;

// ---------------- scratch (device globals; no allocation allowed) ----------------
__device__ float g_h1[256*16*32*32];        // layer1 output [B,16,32,32]
__device__ __half g_Ahi[256*32768];         // fc input, fp16 hi
__device__ __half g_Alo[256*32768];         // fc input, fp16 lo residual
__device__ __half g_Wh[1024ull*32768];      // fc1 weight TRANSPOSED [N,K], fp16
__device__ float g_part[18*256*1024];       // fc1 split-K partials
__device__ float g_fc1[256*1024];           // fc1 output (post relu)

__device__ __forceinline__ uint32_t smem_u32(const void* p) {
    uint32_t a;
    asm("{ .reg .u64 t; cvta.to.shared.u64 t, %1; cvt.u32.u64 %0, t; }" : "=r"(a) : "l"(p));
    return a;
}
__device__ __forceinline__ void ldsm4(uint32_t* r, uint32_t addr) {
    asm volatile("ldmatrix.sync.aligned.m8n8.x4.shared.b16 {%0,%1,%2,%3}, [%4];"
                 : "=r"(r[0]), "=r"(r[1]), "=r"(r[2]), "=r"(r[3]) : "r"(addr));
}
__device__ __forceinline__ void cpa16(uint32_t dst, const void* src) {
    asm volatile("cp.async.ca.shared.global [%0], [%1], 16;" :: "r"(dst), "l"(src));
}
#define CP_COMMIT() asm volatile("cp.async.commit_group;" ::: "memory")
#define CP_WAIT1()  asm volatile("cp.async.wait_group 1;" ::: "memory")
#define MMA_F16(d, a, bb)                                                                      \
    asm volatile("mma.sync.aligned.m16n8k16.row.col.f32.f16.f16.f32 "                          \
        "{%0,%1,%2,%3}, {%4,%5,%6,%7}, {%8,%9}, {%0,%1,%2,%3};"                                \
        : "+f"((d)[0]), "+f"((d)[1]), "+f"((d)[2]), "+f"((d)[3])                               \
        : "r"((a)[0]), "r"((a)[1]), "r"((a)[2]), "r"((a)[3]), "r"((bb)[0]), "r"((bb)[1]))

// ---- packed fp32x2 helpers (sm_100+ PTX; 2x FFMA throughput via FFMA2) ----
__device__ __forceinline__ u64 f2pack(float lo, float hi) {
    u64 d; asm("mov.b64 %0, {%1, %2};" : "=l"(d) : "f"(lo), "f"(hi)); return d;
}
__device__ __forceinline__ void f2unpack(u64 d, float& lo, float& hi) {
    asm("mov.b64 {%0, %1}, %2;" : "=f"(lo), "=f"(hi) : "l"(d));
}
__device__ __forceinline__ u64 ffma2(u64 a, u64 b, u64 c) {
    u64 d; asm("fma.rn.f32x2 %0, %1, %2, %3;" : "=l"(d) : "l"(a), "l"(b), "l"(c)); return d;
}

// =================================================================================
// Fused ConvNN-branch attention layer. grid = B, block = 256 (one thread/token).
// Hot loops use packed f32x2 FMA. Element-wise accumulation chains (B, D-agg, E)
// are bit-identical to the scalar version; only the C/D dot reductions re-pair.
// =================================================================================
template<int CIN, int CU, int R, int D, int CO, int OCC, int OPT2>
__global__ void __launch_bounds__(256, OCC) attn_kernel(
    const float* __restrict__ X,
    const float* __restrict__ Wc, const float* __restrict__ Bc,
    const float* __restrict__ Wq, const float* __restrict__ Wk, const float* __restrict__ Wv,
    const float* __restrict__ Wo, const float* __restrict__ Bo,
    float* __restrict__ Y, __half* __restrict__ Ahi, __half* __restrict__ Alo)
{
    constexpr int NTOK = 256;
    constexpr int NHEADS = 4;
    constexpr int DH = D / NHEADS;
    constexpr int KNN = 9;
    constexpr int DPAD = D + 4;
    constexpr int COUT = CO / 4;
    constexpr int CHUNK = 8;                 // cogs per phase-E register chunk
    constexpr int PROJ = CU*R + 3*CU*D;
    constexpr int WOSZ = (R + D)*CO;
    constexpr int REG0 = OPT2 ? (PROJ > WOSZ ? PROJ : WOSZ) : (PROJ + WOSZ);

    extern __shared__ float smem[];
    float* sWc = smem;
    float* sWq = sWc + CU*R;
    float* sWk = sWq + CU*D;
    float* sWv = sWk + CU*D;
    float* sWo = OPT2 ? smem : (sWv + CU*D);
    float* sBc = smem + REG0;
    float* sBo = sBc + R;
    float* sK  = sBo + CO;
    float* sV  = sK + NTOK*DPAD;

    const int b = blockIdx.x;
    const int n = threadIdx.x;

    for (int idx = n; idx < CU*R; idx += NTOK) sWc[idx] = Wc[idx];
    for (int idx = n; idx < CU*D; idx += NTOK) { sWq[idx]=Wq[idx]; sWk[idx]=Wk[idx]; sWv[idx]=Wv[idx]; }
    if (!OPT2)
        for (int idx = n; idx < WOSZ; idx += NTOK) sWo[idx] = Wo[idx];
    if (n < R)  sBc[n] = Bc[n];
    if (n < CO) sBo[n] = Bo[n];
    __syncthreads();

    const int i = n >> 4;
    const int j = n & 15;

    u64 qp[D/2];
    float loc[R];

    if (OPT2) {
        // ---- pass 1: k/v projections, packed ----
        {
            u64 ka2[D/2], va2[D/2];
            #pragma unroll
            for (int d2 = 0; d2 < D/2; d2++) { ka2[d2] = 0ull; va2[d2] = 0ull; }
            #pragma unroll 4
            for (int c = 0; c < CU; c++) {
                const int ch = c >> 2, si = (c >> 1) & 1, sj = c & 1;
                const float tv = X[((b*CIN + ch)*32 + 2*i + si)*32 + 2*j + sj];
                const u64 tv2 = f2pack(tv, tv);
                const ulonglong2* wk2 = reinterpret_cast<const ulonglong2*>(sWk + c*D);
                const ulonglong2* wv2 = reinterpret_cast<const ulonglong2*>(sWv + c*D);
                #pragma unroll
                for (int d4 = 0; d4 < D/4; d4++) {
                    ulonglong2 wk_ = wk2[d4], wv_ = wv2[d4];
                    ka2[2*d4]   = ffma2(tv2, wk_.x, ka2[2*d4]);
                    ka2[2*d4+1] = ffma2(tv2, wk_.y, ka2[2*d4+1]);
                    va2[2*d4]   = ffma2(tv2, wv_.x, va2[2*d4]);
                    va2[2*d4+1] = ffma2(tv2, wv_.y, va2[2*d4+1]);
                }
            }
            ulonglong2* dk = reinterpret_cast<ulonglong2*>(sK + n*DPAD);
            ulonglong2* dv = reinterpret_cast<ulonglong2*>(sV + n*DPAD);
            #pragma unroll
            for (int d4 = 0; d4 < D/4; d4++) {
                dk[d4] = make_ulonglong2(ka2[2*d4], ka2[2*d4+1]);
                dv[d4] = make_ulonglong2(va2[2*d4], va2[2*d4+1]);
            }
        }
        // ---- pass 2: q (packed) + loc (scalar) ----
        #pragma unroll
        for (int d2 = 0; d2 < D/2; d2++) qp[d2] = 0ull;
        #pragma unroll
        for (int rr = 0; rr < R; rr++) loc[rr] = sBc[rr];
        #pragma unroll 4
        for (int c = 0; c < CU; c++) {
            const int ch = c >> 2, si = (c >> 1) & 1, sj = c & 1;
            const float tv = X[((b*CIN + ch)*32 + 2*i + si)*32 + 2*j + sj];
            const u64 tv2 = f2pack(tv, tv);
            const ulonglong2* wq2 = reinterpret_cast<const ulonglong2*>(sWq + c*D);
            const float4* wc4 = reinterpret_cast<const float4*>(sWc + c*R);
            #pragma unroll
            for (int d4 = 0; d4 < D/4; d4++) {
                ulonglong2 w = wq2[d4];
                qp[2*d4]   = ffma2(tv2, w.x, qp[2*d4]);
                qp[2*d4+1] = ffma2(tv2, w.y, qp[2*d4+1]);
            }
            #pragma unroll
            for (int r4 = 0; r4 < R/4; r4++) {
                float4 w = wc4[r4];
                loc[4*r4]+=tv*w.x; loc[4*r4+1]+=tv*w.y; loc[4*r4+2]+=tv*w.z; loc[4*r4+3]+=tv*w.w;
            }
        }
        #pragma unroll
        for (int rr = 0; rr < R; rr++) loc[rr] = fmaxf(loc[rr], 0.f);
        __syncthreads();   // all proj-weight reads done; K/V visible
        for (int idx = n; idx < WOSZ; idx += NTOK) sWo[idx] = Wo[idx];  // Wo overlay
    } else {
        float q[D], ka[D], va[D];
        #pragma unroll
        for (int dd = 0; dd < D; dd++) { q[dd]=0.f; ka[dd]=0.f; va[dd]=0.f; }
        #pragma unroll
        for (int rr = 0; rr < R; rr++) loc[rr] = sBc[rr];

        #pragma unroll 4
        for (int c = 0; c < CU; c++) {
            const int ch = c >> 2, si = (c >> 1) & 1, sj = c & 1;
            const float tv = X[((b*CIN + ch)*32 + 2*i + si)*32 + 2*j + sj];
            const float4* wq4 = reinterpret_cast<const float4*>(sWq + c*D);
            const float4* wk4 = reinterpret_cast<const float4*>(sWk + c*D);
            const float4* wv4 = reinterpret_cast<const float4*>(sWv + c*D);
            const float4* wc4 = reinterpret_cast<const float4*>(sWc + c*R);
            #pragma unroll
            for (int d4 = 0; d4 < D/4; d4++) {
                float4 w;
                w = wq4[d4]; q[4*d4]+=tv*w.x;  q[4*d4+1]+=tv*w.y;  q[4*d4+2]+=tv*w.z;  q[4*d4+3]+=tv*w.w;
                w = wk4[d4]; ka[4*d4]+=tv*w.x; ka[4*d4+1]+=tv*w.y; ka[4*d4+2]+=tv*w.z; ka[4*d4+3]+=tv*w.w;
                w = wv4[d4]; va[4*d4]+=tv*w.x; va[4*d4+1]+=tv*w.y; va[4*d4+2]+=tv*w.z; va[4*d4+3]+=tv*w.w;
            }
            #pragma unroll
            for (int r4 = 0; r4 < R/4; r4++) {
                float4 w = wc4[r4];
                loc[4*r4]+=tv*w.x; loc[4*r4+1]+=tv*w.y; loc[4*r4+2]+=tv*w.z; loc[4*r4+3]+=tv*w.w;
            }
        }
        #pragma unroll
        for (int rr = 0; rr < R; rr++) loc[rr] = fmaxf(loc[rr], 0.f);
        #pragma unroll
        for (int d4 = 0; d4 < D/4; d4++) {
            reinterpret_cast<float4*>(sK + n*DPAD)[d4] = make_float4(ka[4*d4],ka[4*d4+1],ka[4*d4+2],ka[4*d4+3]);
            reinterpret_cast<float4*>(sV + n*DPAD)[d4] = make_float4(va[4*d4],va[4*d4+1],va[4*d4+2],va[4*d4+3]);
        }
        #pragma unroll
        for (int d2 = 0; d2 < D/2; d2++) qp[d2] = f2pack(q[2*d2], q[2*d2+1]);
        __syncthreads();
    }

    // ---- phase C: sim over all tokens (packed dot) + streaming top-9 ----
    float topv[KNN]; int topi[KNN];
    #pragma unroll
    for (int kk = 0; kk < KNN; kk++) { topv[kk] = -1e30f; topi[kk] = 0; }

    for (int m = 0; m < NTOK; m++) {
        const ulonglong2* kp = reinterpret_cast<const ulonglong2*>(sK + m*DPAD);
        u64 a0 = 0ull, a1 = 0ull;
        #pragma unroll
        for (int d4 = 0; d4 < D/4; d4++) {
            ulonglong2 kv = kp[d4];
            a0 = ffma2(qp[2*d4],   kv.x, a0);
            a1 = ffma2(qp[2*d4+1], kv.y, a1);
        }
        float l0, h0, l1, h1;
        f2unpack(a0, l0, h0); f2unpack(a1, l1, h1);
        const float dot = (l0 + l1) + (h0 + h1);
        if (dot > topv[KNN-1]) {
            topv[KNN-1] = dot; topi[KNN-1] = m;
            #pragma unroll
            for (int jj = KNN-1; jj > 0; --jj) {
                if (topv[jj] > topv[jj-1]) {
                    float tv_ = topv[jj]; topv[jj] = topv[jj-1]; topv[jj-1] = tv_;
                    int   ti_ = topi[jj]; topi[jj] = topi[jj-1]; topi[jj-1] = ti_;
                }
            }
        }
    }

    // ---- phase D: per-head softmax attention over 9 neighbors (packed) ----
    const float scale = 1.0f / sqrtf((float)DH);
    float agg[D];
    #pragma unroll
    for (int h = 0; h < NHEADS; h++) {
        float lg[KNN];
        #pragma unroll
        for (int kk = 0; kk < KNN; kk++) {
            const ulonglong2* kr = reinterpret_cast<const ulonglong2*>(sK + topi[kk]*DPAD + h*DH);
            u64 a0 = 0ull;
            #pragma unroll
            for (int d4 = 0; d4 < DH/4; d4++) {
                ulonglong2 kv = kr[d4];
                a0 = ffma2(qp[h*(DH/2) + 2*d4],     kv.x, a0);
                a0 = ffma2(qp[h*(DH/2) + 2*d4 + 1], kv.y, a0);
            }
            float lo, hi; f2unpack(a0, lo, hi);
            lg[kk] = (lo + hi) * scale;
        }
        float mx = lg[0];
        #pragma unroll
        for (int kk = 1; kk < KNN; kk++) mx = fmaxf(mx, lg[kk]);
        float den = 0.f;
        #pragma unroll
        for (int kk = 0; kk < KNN; kk++) { lg[kk] = expf(lg[kk] - mx); den += lg[kk]; }
        const float inv = 1.0f / den;

        u64 ah2[DH/2];
        #pragma unroll
        for (int d2 = 0; d2 < DH/2; d2++) ah2[d2] = 0ull;
        #pragma unroll
        for (int kk = 0; kk < KNN; kk++) {
            const u64 w2 = f2pack(lg[kk], lg[kk]);
            const ulonglong2* vr = reinterpret_cast<const ulonglong2*>(sV + topi[kk]*DPAD + h*DH);
            #pragma unroll
            for (int d4 = 0; d4 < DH/4; d4++) {
                ulonglong2 vv = vr[d4];
                ah2[2*d4]   = ffma2(w2, vv.x, ah2[2*d4]);
                ah2[2*d4+1] = ffma2(w2, vv.y, ah2[2*d4+1]);
            }
        }
        #pragma unroll
        for (int d2 = 0; d2 < DH/2; d2++) {
            float lo, hi; f2unpack(ah2[d2], lo, hi);
            agg[h*DH + 2*d2]     = lo * inv;
            agg[h*DH + 2*d2 + 1] = hi * inv;
        }
    }

    if (OPT2) {
        __syncthreads();   // Wo overlay loaded (loc already in registers)
    }

    // ---- phase E: concat([local, agg]) @ Wo + bo (packed, chunked) ----
    #pragma unroll 1
    for (int cb = 0; cb < COUT; cb += CHUNK) {
        u64 o01[CHUNK], o23[CHUNK];
        #pragma unroll
        for (int cc = 0; cc < CHUNK; cc++) {
            o01[cc] = f2pack(sBo[4*(cb+cc)+0], sBo[4*(cb+cc)+1]);
            o23[cc] = f2pack(sBo[4*(cb+cc)+2], sBo[4*(cb+cc)+3]);
        }
        #pragma unroll 4
        for (int rr = 0; rr < R; rr++) {
            const u64 lv2 = f2pack(loc[rr], loc[rr]);
            const ulonglong2* wr = reinterpret_cast<const ulonglong2*>(sWo + rr*CO) + cb;
            #pragma unroll
            for (int cc = 0; cc < CHUNK; cc++) {
                ulonglong2 ww = wr[cc];
                o01[cc] = ffma2(lv2, ww.x, o01[cc]);
                o23[cc] = ffma2(lv2, ww.y, o23[cc]);
            }
        }
        #pragma unroll 4
        for (int dd = 0; dd < D; dd++) {
            const u64 av2 = f2pack(agg[dd], agg[dd]);
            const ulonglong2* wr = reinterpret_cast<const ulonglong2*>(sWo + (R+dd)*CO) + cb;
            #pragma unroll
            for (int cc = 0; cc < CHUNK; cc++) {
                ulonglong2 ww = wr[cc];
                o01[cc] = ffma2(av2, ww.x, o01[cc]);
                o23[cc] = ffma2(av2, ww.y, o23[cc]);
            }
        }
        #pragma unroll
        for (int cc = 0; cc < CHUNK; cc++) {
            const int cog = cb + cc;
            float o0, o1, o2, o3;
            f2unpack(o01[cc], o0, o1);
            f2unpack(o23[cc], o2, o3);
            if (Ahi) {
                const size_t base = (size_t)b*32768 + (size_t)cog*1024 + (size_t)(2*i)*32 + 2*j;
                __half h0=__float2half_rn(o0), h1=__float2half_rn(o1);
                __half h2=__float2half_rn(o2), h3=__float2half_rn(o3);
                __half l0=__float2half_rn(o0-__half2float(h0));
                __half l1=__float2half_rn(o1-__half2float(h1));
                __half l2=__float2half_rn(o2-__half2float(h2));
                __half l3=__float2half_rn(o3-__half2float(h3));
                __half2 ph; ph.x=h0; ph.y=h1;
                __half2 pl; pl.x=l0; pl.y=l1;
                *reinterpret_cast<__half2*>(Ahi + base) = ph;
                *reinterpret_cast<__half2*>(Alo + base) = pl;
                ph.x=h2; ph.y=h3; pl.x=l2; pl.y=l3;
                *reinterpret_cast<__half2*>(Ahi + base + 32) = ph;
                *reinterpret_cast<__half2*>(Alo + base + 32) = pl;
            } else {
                float* yb = Y + ((size_t)(b*COUT + cog)*32 + 2*i)*32 + 2*j;
                *reinterpret_cast<float2*>(yb)      = make_float2(o0, o1);
                *reinterpret_cast<float2*>(yb + 32) = make_float2(o2, o3);
            }
        }
    }
}

// =================================================================================
// W [32768,1024] fp32 -> transposed fp16 [1024][32768]
// =================================================================================
__global__ void __launch_bounds__(256) wconv_kernel(
    const float* __restrict__ W, __half* __restrict__ Th)
{
    __shared__ float t[32][33];
    const int k0 = blockIdx.x * 32, n0 = blockIdx.y * 32;
    const int tx = threadIdx.x, ty = threadIdx.y;   // (32,8)
    #pragma unroll
    for (int r = 0; r < 4; r++)
        t[ty + 8*r][tx] = W[(size_t)(k0 + ty + 8*r)*1024 + n0 + tx];
    __syncthreads();
    #pragma unroll
    for (int r = 0; r < 4; r++) {
        const int nn = ty + 8*r;
        Th[(size_t)(n0 + nn)*32768 + k0 + tx] = __float2half_rn(t[tx][nn]);
    }
}

// =================================================================================
// fc1 GEMM via mma.sync fp16 (A hi/lo split -> 2 products; W single fp16).
// CTA tile 128x128, 8 warps (warp 32x64), BK=32.
// cp.async 3-buffer pipeline, 2-stage lookahead, 2 CTAs/SM (92KB smem, 128 regs).
// grid = (8 Ntiles, 2 Mtiles, 18 Ksplits) = 288 CTAs, all resident at occ 2.
// =================================================================================
__global__ void __launch_bounds__(256, 2) fc1_mma(
    const __half* __restrict__ Ahi, const __half* __restrict__ Alo,
    const __half* __restrict__ Wh, float* __restrict__ P)
{
    extern __shared__ char sm[];
    constexpr int KT = 32768;
    constexpr uint32_t TILE = 10240;            // 128 rows * 80 B
    constexpr uint32_t BUFS = 3*TILE;           // Ah | Al | Wh

    const int tid = threadIdx.x, wid = tid >> 5, lane = tid & 31;
    const int lr = lane >> 2, lc = lane & 3;
    const int tr = lane & 7, tq = lane >> 3;
    const int wm = wid & 3, wn = wid >> 2;
    const int m0 = blockIdx.y * 128, n0 = blockIdx.x * 128;
    const int ksp = blockIdx.z;
    const int sbase  = (ksp < 16) ? ksp*57 : 912 + (ksp - 16)*56;
    const int nstage = (ksp < 16) ? 57 : 56;

    const uint32_t smb = smem_u32(sm);
    const uint32_t rowA = (uint32_t)((tr + (tq & 1)*8)*80 + (tq >> 1)*16);
    const uint32_t rowB = (uint32_t)((tr + (tq >> 1)*8)*80 + (tq & 1)*16);

    const int r0g = tid >> 2, c0g = (tid & 3)*8;
    const __half* gAh = Ahi + (size_t)(m0 + r0g)*KT + c0g;
    const __half* gAl = Alo + (size_t)(m0 + r0g)*KT + c0g;
    const __half* gW  = Wh  + (size_t)(n0 + r0g)*KT + c0g;
    const size_t row64 = (size_t)64*KT;
    const uint32_t soff0 = (uint32_t)(r0g*80 + (tid & 3)*16);
    const uint32_t soff1 = soff0 + 64*80;

    float acc[2][8][4];
    #pragma unroll
    for (int mt = 0; mt < 2; mt++)
        #pragma unroll
        for (int nt = 0; nt < 8; nt++)
            #pragma unroll
            for (int e = 0; e < 4; e++) acc[mt][nt][e] = 0.f;

    #pragma unroll
    for (int p = 0; p < 2; p++) {
        const uint32_t b = smb + (uint32_t)p*BUFS;
        const int kk = (sbase + p)*32;
        cpa16(b + soff0,          gAh + kk);
        cpa16(b + soff1,          gAh + row64 + kk);
        cpa16(b + TILE + soff0,   gAl + kk);
        cpa16(b + TILE + soff1,   gAl + row64 + kk);
        cpa16(b + 2*TILE + soff0, gW + kk);
        cpa16(b + 2*TILE + soff1, gW + row64 + kk);
        CP_COMMIT();
    }

    int bufc = 0, bufn = 2;
    for (int s = 0; s < nstage; s++) {
        CP_WAIT1();
        __syncthreads();
        if (s + 2 < nstage) {
            const uint32_t b = smb + (uint32_t)bufn*BUFS;
            const int kk = (sbase + s + 2)*32;
            cpa16(b + soff0,          gAh + kk);
            cpa16(b + soff1,          gAh + row64 + kk);
            cpa16(b + TILE + soff0,   gAl + kk);
            cpa16(b + TILE + soff1,   gAl + row64 + kk);
            cpa16(b + 2*TILE + soff0, gW + kk);
            cpa16(b + 2*TILE + soff1, gW + row64 + kk);
            CP_COMMIT();
        }
        const uint32_t base = smb + (uint32_t)bufc*BUFS;
        bufc = (bufc + 1 == 3) ? 0 : bufc + 1;
        bufn = (bufn + 1 == 3) ? 0 : bufn + 1;
        const uint32_t aH = base + (uint32_t)(wm*32)*80 + rowA;
        const uint32_t aL = aH + TILE;
        const uint32_t bB = base + 2*TILE + (uint32_t)(wn*64)*80 + rowB;
        #pragma unroll
        for (int ks = 0; ks < 2; ks++) {
            const uint32_t kb = ks*32;
            uint32_t afh[2][4], afl[2][4], bfr[4][4];
            ldsm4(afh[0], aH + kb);            ldsm4(afh[1], aH + 16*80 + kb);
            ldsm4(afl[0], aL + kb);            ldsm4(afl[1], aL + 16*80 + kb);
            #pragma unroll
            for (int p = 0; p < 4; p++) ldsm4(bfr[p], bB + (uint32_t)(p*16)*80 + kb);
            #pragma unroll
            for (int mt = 0; mt < 2; mt++)
                #pragma unroll
                for (int nt = 0; nt < 8; nt++) {
                    uint32_t* bb = &bfr[nt >> 1][(nt & 1)*2];
                    MMA_F16(acc[mt][nt], afh[mt], bb);
                    MMA_F16(acc[mt][nt], afl[mt], bb);
                }
        }
    }

    float* Pp = P + (size_t)ksp * 262144;
    #pragma unroll
    for (int mt = 0; mt < 2; mt++) {
        const int r = m0 + wm*32 + mt*16 + lr;
        #pragma unroll
        for (int nt = 0; nt < 8; nt++) {
            const int cc = n0 + wn*64 + nt*8 + lc*2;
            *(float2*)(Pp + (size_t)r*1024 + cc)       = make_float2(acc[mt][nt][0], acc[mt][nt][1]);
            *(float2*)(Pp + (size_t)(r + 8)*1024 + cc) = make_float2(acc[mt][nt][2], acc[mt][nt][3]);
        }
    }
}

// fc1 partial reduction + bias + relu
__global__ void fc1_reduce(const float* __restrict__ P, const float* __restrict__ Bb,
                           float* __restrict__ O)
{
    const int idx = blockIdx.x * blockDim.x + threadIdx.x;   // 262144 total
    float s = Bb[idx & 1023];
    #pragma unroll
    for (int sp = 0; sp < 18; sp++) s += P[sp*262144 + idx];
    O[idx] = fmaxf(s, 0.f);
}

// fc2: [256,1024] @ [1024,10] + b
__global__ void fc2_kernel(const float* __restrict__ H, const float* __restrict__ W,
                           const float* __restrict__ Bb, float* __restrict__ out)
{
    const int b = blockIdx.x, tid = threadIdx.x;
    float acc[10];
    #pragma unroll
    for (int o = 0; o < 10; o++) acc[o] = 0.f;
    for (int k = tid; k < 1024; k += 128) {
        const float hv = H[b*1024 + k];
        const float* wr = W + k*10;
        #pragma unroll
        for (int o = 0; o < 10; o++) acc[o] += hv * wr[o];
    }
    __shared__ float red[4][10];
    #pragma unroll
    for (int o = 0; o < 10; o++) {
        #pragma unroll
        for (int off = 16; off; off >>= 1)
            acc[o] += __shfl_down_sync(0xffffffffu, acc[o], off);
    }
    if ((tid & 31) == 0) {
        #pragma unroll
        for (int o = 0; o < 10; o++) red[tid >> 5][o] = acc[o];
    }
    __syncthreads();
    if (tid < 10)
        out[b*10 + tid] = Bb[tid] + red[0][tid] + red[1][tid] + red[2][tid] + red[3][tid];
}

// =================================================================================
extern "C" void kernel_launch(void* const* d_in, const int* in_sizes, int n_in,
                              void* d_out, int out_size)
{
    const float* x    = (const float*)d_in[0];
    const float* w1c  = (const float*)d_in[1];
    const float* b1c  = (const float*)d_in[2];
    const float* w1q  = (const float*)d_in[3];
    const float* w1k  = (const float*)d_in[4];
    const float* w1v  = (const float*)d_in[5];
    const float* w1o  = (const float*)d_in[6];
    const float* b1o  = (const float*)d_in[7];
    const float* w2c  = (const float*)d_in[8];
    const float* b2c  = (const float*)d_in[9];
    const float* w2q  = (const float*)d_in[10];
    const float* w2k  = (const float*)d_in[11];
    const float* w2v  = (const float*)d_in[12];
    const float* w2o  = (const float*)d_in[13];
    const float* b2o  = (const float*)d_in[14];
    const float* fc1w = (const float*)d_in[15];
    const float* fc1b = (const float*)d_in[16];
    const float* fc2w = (const float*)d_in[17];
    const float* fc2b = (const float*)d_in[18];
    float* out = (float*)d_out;

    float *h1, *part, *fch;
    __half *ahi, *alo, *wh;
    cudaGetSymbolAddress((void**)&h1,   g_h1);
    cudaGetSymbolAddress((void**)&ahi,  g_Ahi);
    cudaGetSymbolAddress((void**)&alo,  g_Alo);
    cudaGetSymbolAddress((void**)&wh,   g_Wh);
    cudaGetSymbolAddress((void**)&part, g_part);
    cudaGetSymbolAddress((void**)&fch,  g_fc1);

    const int SM1 = (12*16 + 3*12*16 + (16+16)*64 + 16 + 64 + 2*256*(16+4)) * 4;
    const int SM2 = (8192 + 32 + 128 + 2*256*(32+4)) * 4;
    const int SMG = 3 * 3 * 10240;   // 92160

    cudaFuncSetAttribute(attn_kernel<3,12,16,16,64,2,0>,
                         cudaFuncAttributeMaxDynamicSharedMemorySize, SM1);
    cudaFuncSetAttribute(attn_kernel<16,64,32,32,128,2,1>,
                         cudaFuncAttributeMaxDynamicSharedMemorySize, SM2);
    cudaFuncSetAttribute(fc1_mma,
                         cudaFuncAttributeMaxDynamicSharedMemorySize, SMG);

    // ---- fork-join: wconv (DRAM-bound) overlaps attn1+attn2 (compute-bound) ----
    cudaStream_t s1;
    cudaStreamCreateWithFlags(&s1, cudaStreamNonBlocking);
    cudaEvent_t e0, e1;
    cudaEventCreateWithFlags(&e0, cudaEventDisableTiming);
    cudaEventCreateWithFlags(&e1, cudaEventDisableTiming);

    cudaEventRecord(e0, 0);
    cudaStreamWaitEvent(s1, e0, 0);
    wconv_kernel<<<dim3(1024, 32), dim3(32, 8), 0, s1>>>(fc1w, wh);
    cudaEventRecord(e1, s1);

    attn_kernel<3,12,16,16,64,2,0><<<256, 256, SM1>>>(x,  w1c, b1c, w1q, w1k, w1v, w1o, b1o,
                                                  h1, nullptr, nullptr);
    attn_kernel<16,64,32,32,128,2,1><<<256, 256, SM2>>>(h1, w2c, b2c, w2q, w2k, w2v, w2o, b2o,
                                                  nullptr, ahi, alo);

    cudaStreamWaitEvent(0, e1, 0);
    fc1_mma<<<dim3(8, 2, 18), 256, SMG>>>(ahi, alo, wh, part);
    fc1_reduce<<<1024, 256>>>(part, fc1b, fch);
    fc2_kernel<<<256, 128>>>(fch, fc2w, fc2b, out);
}